// round 1
// baseline (speedup 1.0000x reference)
#include <cuda_runtime.h>
#include <math.h>

// Problem dims
#define BB 16
#define SS 128
#define VV 40000
#define DD 768
#define HH 12
#define HD 64
#define FF 3072
#define LL 12

// ---------------- scratch (static device globals; no allocation) ----------------
__device__ float g_h   [BB*SS*DD];   // residual stream  [2048,768]
__device__ float g_q   [BB*SS*DD];   // q as [b,s,h,e]
__device__ float g_k   [BB*SS*DD];
__device__ float g_v   [BB*SS*DD];
__device__ float g_attn[BB*SS*DD];   // concat-head attention out [b,s,h*e]
__device__ float g_proj[BB*SS*DD];
__device__ float g_ff1 [BB*SS*FF];
__device__ float g_ff2 [BB*SS*DD];

// ---------------- embedding ----------------
__global__ void embed_kernel(const int* __restrict__ x,
                             const float* __restrict__ bpe,
                             const float* __restrict__ pe) {
    int idx = blockIdx.x * blockDim.x + threadIdx.x;
    if (idx >= BB*SS*DD) return;
    int d  = idx % DD;
    int bs = idx / DD;
    int s  = bs % SS;
    int tok = x[bs];
    g_h[idx] = bpe[(long)tok*DD + d] + pe[s*DD + d];
}

// ---------------- generic tiled GEMM: C = A[MxK] * B[KxN] + bias ----------------
// 64x64 tile, BK=16, 256 threads, 4x4 microtile, float4 smem reads.
// grid: (M/64, N/64, Z). Per-z offsets for B, C, bias (batched heads).
// Requires M%64==0, N%64==0, K%16==0 (true for all call sites here).
__global__ __launch_bounds__(256) void gemm64(
    const float* __restrict__ A, const float* __restrict__ Bm,
    float* __restrict__ C, const float* __restrict__ bias,
    int M, int N, int K, int lda, int ldb, int ldc,
    long sBz, long sCz, long sbz)
{
    const int z = blockIdx.z;
    const float* Bp   = Bm   + (long)z * sBz;
    float*       Cp   = C    + (long)z * sCz;
    const float* bp   = bias + (long)z * sbz;

    const int m0 = blockIdx.x * 64;
    const int n0 = blockIdx.y * 64;
    const int tid = threadIdx.x;
    const int tx = tid & 15;        // 0..15 -> 4 cols each
    const int ty = tid >> 4;        // 0..15 -> 4 rows each

    __shared__ float As[16][68];    // [k][m], padded: 68*4=272 bytes, 16B-aligned rows
    __shared__ float Bs[16][68];    // [k][n]

    float acc[4][4] = {};

    for (int k0 = 0; k0 < K; k0 += 16) {
        // load A tile 64x16 -> As[k][m]  (coalesced global reads)
        #pragma unroll
        for (int i = 0; i < 4; i++) {
            int idx = tid + i * 256;
            int r = idx >> 4, c = idx & 15;
            As[c][r] = A[(long)(m0 + r) * lda + k0 + c];
        }
        // load B tile 16x64 -> Bs[k][n]
        #pragma unroll
        for (int i = 0; i < 4; i++) {
            int idx = tid + i * 256;
            int r = idx >> 6, c = idx & 63;
            Bs[r][c] = Bp[(long)(k0 + r) * ldb + n0 + c];
        }
        __syncthreads();
        #pragma unroll
        for (int kk = 0; kk < 16; kk++) {
            float4 av = *reinterpret_cast<const float4*>(&As[kk][ty * 4]);
            float4 bv = *reinterpret_cast<const float4*>(&Bs[kk][tx * 4]);
            float a[4] = {av.x, av.y, av.z, av.w};
            float b[4] = {bv.x, bv.y, bv.z, bv.w};
            #pragma unroll
            for (int i = 0; i < 4; i++)
                #pragma unroll
                for (int j = 0; j < 4; j++)
                    acc[i][j] += a[i] * b[j];
        }
        __syncthreads();
    }

    const int cbase = n0 + tx * 4;
    float4 bias4;
    bias4.x = bp[cbase + 0]; bias4.y = bp[cbase + 1];
    bias4.z = bp[cbase + 2]; bias4.w = bp[cbase + 3];
    #pragma unroll
    for (int i = 0; i < 4; i++) {
        int r = m0 + ty * 4 + i;
        float4 out;
        out.x = acc[i][0] + bias4.x;
        out.y = acc[i][1] + bias4.y;
        out.z = acc[i][2] + bias4.z;
        out.w = acc[i][3] + bias4.w;
        *reinterpret_cast<float4*>(&Cp[(long)r * ldc + cbase]) = out;
    }
}

// ---------------- attention: scores + mask + softmax + AV, one block per (b,h,q) ----------------
__global__ __launch_bounds__(128) void attn_kernel(const int* __restrict__ ignore) {
    const int qi = blockIdx.x & (SS - 1);
    const int h  = (blockIdx.x >> 7) % HH;
    const int b  = blockIdx.x / (SS * HH);
    const int t  = threadIdx.x;   // 0..127, one per key

    __shared__ float qrow[HD];
    __shared__ float p[SS];
    __shared__ float red[SS];

    const float* qptr = g_q + ((long)(b * SS + qi) * DD + h * HD);
    if (t < HD) qrow[t] = qptr[t];
    __syncthreads();

    const bool allowed = (t <= qi) && (ignore[b * SS + t] == 0 || t == qi);
    float score = -INFINITY;
    if (allowed) {
        const float* kptr = g_k + ((long)(b * SS + t) * DD + h * HD);
        float s = 0.f;
        #pragma unroll
        for (int e = 0; e < HD; e++) s += qrow[e] * kptr[e];
        score = s * 0.125f;   // 1/sqrt(64)
    }

    // max reduce
    red[t] = score; __syncthreads();
    for (int off = 64; off > 0; off >>= 1) {
        if (t < off) red[t] = fmaxf(red[t], red[t + off]);
        __syncthreads();
    }
    const float mx = red[0];
    __syncthreads();

    const float e = allowed ? expf(score - mx) : 0.f;
    p[t] = e; red[t] = e; __syncthreads();
    for (int off = 64; off > 0; off >>= 1) {
        if (t < off) red[t] += red[t + off];
        __syncthreads();
    }
    const float inv = 1.f / red[0];

    if (t < HD) {
        const float* vbase = g_v + ((long)b * SS * DD + h * HD + t);
        float o = 0.f;
        #pragma unroll 4
        for (int k = 0; k < SS; k++) o += p[k] * vbase[(long)k * DD];
        g_attn[(long)(b * SS + qi) * DD + h * HD + t] = o * inv;
    }
}

// ---------------- residual (+optional exact GELU) + LayerNorm, in-place on g_h ----------------
__global__ __launch_bounds__(256) void add_ln_kernel(
    const float* __restrict__ res_in,
    const float* __restrict__ w, const float* __restrict__ bvec,
    int dogelu)
{
    const int row = blockIdx.x;
    const int t = threadIdx.x;
    __shared__ float red[256];

    float vals[3];
    float sum = 0.f;
    #pragma unroll
    for (int i = 0; i < 3; i++) {
        int d = t + i * 256;
        float r = res_in[(long)row * DD + d];
        if (dogelu) r = 0.5f * r * (1.f + erff(r * 0.70710678118f));
        float v = g_h[(long)row * DD + d] + r;
        vals[i] = v;
        sum += v;
    }
    red[t] = sum; __syncthreads();
    for (int off = 128; off > 0; off >>= 1) {
        if (t < off) red[t] += red[t + off];
        __syncthreads();
    }
    const float mean = red[0] * (1.f / DD);
    __syncthreads();

    float vs = 0.f;
    #pragma unroll
    for (int i = 0; i < 3; i++) {
        float dv = vals[i] - mean;
        vs += dv * dv;
    }
    red[t] = vs; __syncthreads();
    for (int off = 128; off > 0; off >>= 1) {
        if (t < off) red[t] += red[t + off];
        __syncthreads();
    }
    const float rstd = rsqrtf(red[0] * (1.f / DD) + 1e-5f);

    #pragma unroll
    for (int i = 0; i < 3; i++) {
        int d = t + i * 256;
        g_h[(long)row * DD + d] = (vals[i] - mean) * rstd * w[d] + bvec[d];
    }
}

// ---------------- host orchestration ----------------
extern "C" void kernel_launch(void* const* d_in, const int* in_sizes, int n_in,
                              void* d_out, int out_size) {
    const int*   x     = (const int*)  d_in[0];
    const int*   ign   = (const int*)  d_in[1];
    const float* bpe   = (const float*)d_in[2];
    const float* pe    = (const float*)d_in[3];
    const float* Wq    = (const float*)d_in[4];
    const float* bq    = (const float*)d_in[5];
    const float* Wk    = (const float*)d_in[6];
    const float* bk    = (const float*)d_in[7];
    const float* Wv    = (const float*)d_in[8];
    const float* bv    = (const float*)d_in[9];
    const float* Wo    = (const float*)d_in[10];
    const float* bo    = (const float*)d_in[11];
    const float* W1    = (const float*)d_in[12];
    const float* b1    = (const float*)d_in[13];
    const float* W2    = (const float*)d_in[14];
    const float* b2    = (const float*)d_in[15];
    const float* ln1w  = (const float*)d_in[16];
    const float* ln1b  = (const float*)d_in[17];
    const float* ln2w  = (const float*)d_in[18];
    const float* ln2b  = (const float*)d_in[19];
    const float* Wout  = (const float*)d_in[20];
    const float* bout  = (const float*)d_in[21];
    float* out = (float*)d_out;

    float *gh, *gq, *gk, *gv, *gattn, *gproj, *gff1, *gff2;
    cudaGetSymbolAddress((void**)&gh,    g_h);
    cudaGetSymbolAddress((void**)&gq,    g_q);
    cudaGetSymbolAddress((void**)&gk,    g_k);
    cudaGetSymbolAddress((void**)&gv,    g_v);
    cudaGetSymbolAddress((void**)&gattn, g_attn);
    cudaGetSymbolAddress((void**)&gproj, g_proj);
    cudaGetSymbolAddress((void**)&gff1,  g_ff1);
    cudaGetSymbolAddress((void**)&gff2,  g_ff2);

    const int M = BB * SS;   // 2048

    // embedding
    embed_kernel<<<(BB*SS*DD + 255) / 256, 256>>>(x, bpe, pe);

    for (int l = 0; l < LL; l++) {
        const float* WqL = Wq + (long)l * HH * DD * HD;
        const float* WkL = Wk + (long)l * HH * DD * HD;
        const float* WvL = Wv + (long)l * HH * DD * HD;
        const float* bqL = bq + (long)l * HH * HD;
        const float* bkL = bk + (long)l * HH * HD;
        const float* bvL = bv + (long)l * HH * HD;

        // QKV: per-head batched GEMM [2048,768]x[768,64] (z = head)
        dim3 gqkv(M / 64, 1, HH);
        gemm64<<<gqkv, 256>>>(gh, WqL, gq, bqL, M, HD, DD, DD, HD, DD,
                              (long)DD * HD, (long)HD, (long)HD);
        gemm64<<<gqkv, 256>>>(gh, WkL, gk, bkL, M, HD, DD, DD, HD, DD,
                              (long)DD * HD, (long)HD, (long)HD);
        gemm64<<<gqkv, 256>>>(gh, WvL, gv, bvL, M, HD, DD, DD, HD, DD,
                              (long)DD * HD, (long)HD, (long)HD);

        // attention
        attn_kernel<<<BB * HH * SS, 128>>>(ign);

        // output projection
        gemm64<<<dim3(M / 64, DD / 64, 1), 256>>>(gattn, Wo + (long)l * DD * DD,
                                                  gproj, bo + (long)l * DD,
                                                  M, DD, DD, DD, DD, DD, 0, 0, 0);
        // h = LN(h + proj)
        add_ln_kernel<<<M, 256>>>(gproj, ln1w + (long)l * DD, ln1b + (long)l * DD, 0);

        // FF
        gemm64<<<dim3(M / 64, FF / 64, 1), 256>>>(gh, W1 + (long)l * DD * FF,
                                                  gff1, b1 + (long)l * FF,
                                                  M, FF, DD, DD, FF, FF, 0, 0, 0);
        gemm64<<<dim3(M / 64, DD / 64, 1), 256>>>(gff1, W2 + (long)l * FF * DD,
                                                  gff2, b2 + (long)l * DD,
                                                  M, DD, FF, FF, DD, DD, 0, 0, 0);
        // h = LN(h + gelu(ff2))
        add_ln_kernel<<<M, 256>>>(gff2, ln2w + (long)l * DD, ln2b + (long)l * DD, 1);
    }

    // logits: [2048,768] x [768,40000]
    gemm64<<<dim3(M / 64, VV / 64, 1), 256>>>(gh, Wout, out, bout,
                                              M, VV, DD, DD, VV, VV, 0, 0, 0);
}

// round 4
// speedup vs baseline: 1.7837x; 1.7837x over previous
#include <cuda_runtime.h>
#include <cuda_bf16.h>
#include <math.h>
#include <stdint.h>

#define BB 16
#define SS 128
#define VV 40000
#define DD 768
#define HH 12
#define HD 64
#define FF 3072
#define LL 12

typedef __nv_bfloat16 bf16;

// ---------------- fp32 scratch ----------------
__device__ float g_h   [BB*SS*DD];
__device__ float g_q   [BB*SS*DD];
__device__ float g_k   [BB*SS*DD];
__device__ float g_v   [BB*SS*DD];
__device__ float g_attn[BB*SS*DD];
__device__ float g_proj[BB*SS*DD];
__device__ float g_ff1 [BB*SS*FF];
__device__ float g_ff2 [BB*SS*DD];

// ---------------- bf16 split weights, transposed to [N][K] ----------------
__device__ bf16 s_wq [2][LL*DD*DD];
__device__ bf16 s_wk [2][LL*DD*DD];
__device__ bf16 s_wv [2][LL*DD*DD];
__device__ bf16 s_wo [2][LL*DD*DD];
__device__ bf16 s_w1 [2][LL*DD*FF];
__device__ bf16 s_w2 [2][LL*FF*DD];
__device__ bf16 s_wout[2][VV*DD];
__device__ bf16 s_act [2][BB*SS*FF];

// ======================= helpers =======================
__device__ __forceinline__ uint32_t smem_u32(const void* p) {
    uint32_t a;
    asm("{ .reg .u64 t; cvta.to.shared.u64 t, %1; cvt.u32.u64 %0, t; }" : "=r"(a) : "l"(p));
    return a;
}
__device__ __forceinline__ void cp16(uint32_t dst, const void* src) {
    asm volatile("cp.async.cg.shared.global [%0], [%1], 16;" :: "r"(dst), "l"(src) : "memory");
}
__device__ __forceinline__ void zero16(uint32_t dst) {
    asm volatile("st.shared.v4.b32 [%0], {%1,%1,%1,%1};" :: "r"(dst), "r"(0u) : "memory");
}
__device__ __forceinline__ void cp_commit() {
    asm volatile("cp.async.commit_group;" ::: "memory");
}
__device__ __forceinline__ void ldm4(uint32_t addr, uint32_t* r) {
    asm volatile("ldmatrix.sync.aligned.m8n8.x4.shared.b16 {%0,%1,%2,%3}, [%4];"
                 : "=r"(r[0]), "=r"(r[1]), "=r"(r[2]), "=r"(r[3]) : "r"(addr));
}
__device__ __forceinline__ void mma16816(float* d, const uint32_t* a, uint32_t b0, uint32_t b1) {
    asm volatile(
        "mma.sync.aligned.m16n8k16.row.col.f32.bf16.bf16.f32 "
        "{%0,%1,%2,%3}, {%4,%5,%6,%7}, {%8,%9}, {%0,%1,%2,%3};"
        : "+f"(d[0]), "+f"(d[1]), "+f"(d[2]), "+f"(d[3])
        : "r"(a[0]), "r"(a[1]), "r"(a[2]), "r"(a[3]), "r"(b0), "r"(b1));
}

// ======================= small kernels =======================
__global__ void embed_kernel(const int* __restrict__ x,
                             const float* __restrict__ bpe,
                             const float* __restrict__ pe) {
    int idx = blockIdx.x * blockDim.x + threadIdx.x;
    if (idx >= BB*SS*DD) return;
    int d  = idx % DD;
    int bs = idx / DD;
    int s  = bs % SS;
    int tok = x[bs];
    g_h[idx] = bpe[(long)tok*DD + d] + pe[s*DD + d];
}

__global__ void conv_act(const float* __restrict__ s, bf16* __restrict__ hi,
                         bf16* __restrict__ lo, int n) {
    int i = blockIdx.x * blockDim.x + threadIdx.x;
    if (i >= n) return;
    float v = s[i];
    bf16 h = __float2bfloat16(v);
    hi[i] = h;
    lo[i] = __float2bfloat16(v - __bfloat162float(h));
}

// transpose + split: src fp32 [R][C] (z-batched) -> dst bf16 [C][R] hi/lo
__global__ void conv_transpose(const float* __restrict__ src, bf16* __restrict__ dhi,
                               bf16* __restrict__ dlo, int R, int C,
                               long srcZ, long dstZ) {
    __shared__ float t[32][33];
    int c0 = blockIdx.x * 32, r0 = blockIdx.y * 32;
    long zs = (long)blockIdx.z * srcZ, zd = (long)blockIdx.z * dstZ;
    int tx = threadIdx.x, ty = threadIdx.y;
    #pragma unroll
    for (int i = 0; i < 4; i++)
        t[ty + i*8][tx] = src[zs + (long)(r0 + ty + i*8) * C + c0 + tx];
    __syncthreads();
    #pragma unroll
    for (int i = 0; i < 4; i++) {
        int cc = ty + i*8;
        float v = t[tx][cc];
        bf16 h = __float2bfloat16(v);
        long o = zd + (long)(c0 + cc) * R + r0 + tx;
        dhi[o] = h;
        dlo[o] = __float2bfloat16(v - __bfloat162float(h));
    }
}

// ======================= HMMA split-bf16 GEMM =======================
// C[2048, N] = (Ah+Al)[2048,K] x (Bh+Bl)^T + bias ; B stored [N][K].
// 128x128 tile, K-chunk 32, cp.async double buffer, 8 warps (2m x 4n), 64x32/warp.
#define TROW 80                        // padded row: 32 bf16 + 8 pad = 80 bytes
#define MAT_BYTES (128 * TROW)         // 10240
#define BUF_BYTES (4 * MAT_BYTES)      // AH, AL, BH, BL
#define GH_SMEM   (2 * BUF_BYTES)      // 81920

__device__ __forceinline__ void load_chunk(
    uint32_t base, const bf16* __restrict__ Ah, const bf16* __restrict__ Al,
    const bf16* __restrict__ Bh, const bf16* __restrict__ Bl,
    int m0, int n0, int N, int K, int c, int tid)
{
    uint32_t bb = base + (uint32_t)(c & 1) * BUF_BYTES;
    int k0 = c << 5;
    #pragma unroll
    for (int i = 0; i < 2; i++) {
        int ci  = tid + i * 256;          // 0..511
        int row = ci >> 2, kq = ci & 3;
        uint32_t doff = (uint32_t)(row * TROW + kq * 16);
        long aoff = (long)(m0 + row) * K + k0 + kq * 8;
        cp16(bb + 0 * MAT_BYTES + doff, Ah + aoff);
        cp16(bb + 1 * MAT_BYTES + doff, Al + aoff);
        int nr = n0 + row;
        if (nr < N) {
            long boff = (long)nr * K + k0 + kq * 8;
            cp16(bb + 2 * MAT_BYTES + doff, Bh + boff);
            cp16(bb + 3 * MAT_BYTES + doff, Bl + boff);
        } else {
            zero16(bb + 2 * MAT_BYTES + doff);
            zero16(bb + 3 * MAT_BYTES + doff);
        }
    }
}

__global__ __launch_bounds__(256) void gemm_hmma(
    const bf16* __restrict__ Ah, const bf16* __restrict__ Al,
    const bf16* __restrict__ Bh, const bf16* __restrict__ Bl,
    const float* __restrict__ bias, float* __restrict__ C,
    int N, int K)
{
    extern __shared__ char smem[];
    const uint32_t base = smem_u32(smem);
    const int tid  = threadIdx.x;
    const int lane = tid & 31;
    const int w    = tid >> 5;
    const int wm   = w & 1;          // 2 m-slots of 64
    const int wn   = w >> 1;         // 4 n-slots of 32
    const int m0 = blockIdx.x * 128, n0 = blockIdx.y * 128;
    const int nCh = K >> 5;

    float acc[4][4][4];
    #pragma unroll
    for (int i = 0; i < 4; i++)
        #pragma unroll
        for (int j = 0; j < 4; j++)
            #pragma unroll
            for (int q = 0; q < 4; q++) acc[i][j][q] = 0.f;

    // ldmatrix per-lane offsets
    const uint32_t a_loff = (uint32_t)((lane & 15) * TROW + ((lane >> 4) << 3) * 2);
    const uint32_t b_loff = (uint32_t)((((lane & 7) + ((lane & 16) ? 8 : 0)) * TROW) +
                                       ((lane & 8) ? 16 : 0));

    load_chunk(base, Ah, Al, Bh, Bl, m0, n0, N, K, 0, tid);
    cp_commit();

    for (int c = 0; c < nCh; c++) {
        if (c + 1 < nCh) {
            load_chunk(base, Ah, Al, Bh, Bl, m0, n0, N, K, c + 1, tid);
            cp_commit();
            asm volatile("cp.async.wait_group 1;" ::: "memory");
        } else {
            asm volatile("cp.async.wait_group 0;" ::: "memory");
        }
        __syncthreads();

        uint32_t bb = base + (uint32_t)(c & 1) * BUF_BYTES;
        uint32_t aH = bb + 0 * MAT_BYTES + (uint32_t)(wm * 64) * TROW;
        uint32_t aL = bb + 1 * MAT_BYTES + (uint32_t)(wm * 64) * TROW;
        uint32_t bH = bb + 2 * MAT_BYTES + (uint32_t)(wn * 32) * TROW;
        uint32_t bL = bb + 3 * MAT_BYTES + (uint32_t)(wn * 32) * TROW;

        #pragma unroll
        for (int ks = 0; ks < 2; ks++) {
            const uint32_t koff = (uint32_t)(ks * 16 * 2);   // 16 bf16 = 32 bytes
            uint32_t ah[4][4], al[4][4], bh[2][4], bl[2][4];
            #pragma unroll
            for (int mi = 0; mi < 4; mi++) {
                ldm4(aH + (uint32_t)(mi * 16) * TROW + a_loff + koff, ah[mi]);
                ldm4(aL + (uint32_t)(mi * 16) * TROW + a_loff + koff, al[mi]);
            }
            #pragma unroll
            for (int g = 0; g < 2; g++) {
                ldm4(bH + (uint32_t)(g * 16) * TROW + b_loff + koff, bh[g]);
                ldm4(bL + (uint32_t)(g * 16) * TROW + b_loff + koff, bl[g]);
            }
            #pragma unroll
            for (int mi = 0; mi < 4; mi++) {
                #pragma unroll
                for (int ni = 0; ni < 4; ni++) {
                    const int g = ni >> 1, o = (ni & 1) * 2;
                    mma16816(acc[mi][ni], ah[mi], bh[g][o], bh[g][o + 1]);
                    mma16816(acc[mi][ni], ah[mi], bl[g][o], bl[g][o + 1]);
                    mma16816(acc[mi][ni], al[mi], bh[g][o], bh[g][o + 1]);
                }
            }
        }
        __syncthreads();
    }

    // epilogue
    #pragma unroll
    for (int mi = 0; mi < 4; mi++) {
        int row = m0 + wm * 64 + mi * 16 + (lane >> 2);
        #pragma unroll
        for (int ni = 0; ni < 4; ni++) {
            int col = n0 + wn * 32 + ni * 8 + ((lane & 3) << 1);
            if (col < N) {
                float bx = bias[col], by = bias[col + 1];
                float2 v0 = make_float2(acc[mi][ni][0] + bx, acc[mi][ni][1] + by);
                float2 v1 = make_float2(acc[mi][ni][2] + bx, acc[mi][ni][3] + by);
                *reinterpret_cast<float2*>(C + (long)row * N + col)       = v0;
                *reinterpret_cast<float2*>(C + (long)(row + 8) * N + col) = v1;
            }
        }
    }
}

// ======================= attention =======================
__global__ __launch_bounds__(128) void attn_kernel(const int* __restrict__ ignore) {
    const int qi = blockIdx.x & (SS - 1);
    const int h  = (blockIdx.x >> 7) % HH;
    const int b  = blockIdx.x / (SS * HH);
    const int t  = threadIdx.x;

    __shared__ float qrow[HD];
    __shared__ float p[SS];
    __shared__ float red[SS];

    const float* qptr = g_q + ((long)(b * SS + qi) * DD + h * HD);
    if (t < HD) qrow[t] = qptr[t];
    __syncthreads();

    const bool allowed = (t <= qi) && (ignore[b * SS + t] == 0 || t == qi);
    float score = -INFINITY;
    if (allowed) {
        const float* kptr = g_k + ((long)(b * SS + t) * DD + h * HD);
        float s = 0.f;
        #pragma unroll
        for (int e = 0; e < HD; e++) s += qrow[e] * kptr[e];
        score = s * 0.125f;
    }
    red[t] = score; __syncthreads();
    for (int off = 64; off > 0; off >>= 1) {
        if (t < off) red[t] = fmaxf(red[t], red[t + off]);
        __syncthreads();
    }
    const float mx = red[0];
    __syncthreads();
    const float e = allowed ? expf(score - mx) : 0.f;
    p[t] = e; red[t] = e; __syncthreads();
    for (int off = 64; off > 0; off >>= 1) {
        if (t < off) red[t] += red[t + off];
        __syncthreads();
    }
    const float inv = 1.f / red[0];
    if (t < HD) {
        const float* vbase = g_v + ((long)b * SS * DD + h * HD + t);
        float o = 0.f;
        #pragma unroll 4
        for (int k = 0; k < SS; k++) o += p[k] * vbase[(long)k * DD];
        g_attn[(long)(b * SS + qi) * DD + h * HD + t] = o * inv;
    }
}

// ======================= residual (+GELU) + LayerNorm =======================
__global__ __launch_bounds__(256) void add_ln_kernel(
    const float* __restrict__ res_in,
    const float* __restrict__ w, const float* __restrict__ bvec,
    int dogelu) {
    const int row = blockIdx.x;
    const int t = threadIdx.x;
    __shared__ float red[256];

    float vals[3];
    float sum = 0.f;
    #pragma unroll
    for (int i = 0; i < 3; i++) {
        int d = t + i * 256;
        float r = res_in[(long)row * DD + d];
        if (dogelu) r = 0.5f * r * (1.f + erff(r * 0.70710678118f));
        float v = g_h[(long)row * DD + d] + r;
        vals[i] = v;
        sum += v;
    }
    red[t] = sum; __syncthreads();
    for (int off = 128; off > 0; off >>= 1) {
        if (t < off) red[t] += red[t + off];
        __syncthreads();
    }
    const float mean = red[0] * (1.f / DD);
    __syncthreads();
    float vs = 0.f;
    #pragma unroll
    for (int i = 0; i < 3; i++) { float dv = vals[i] - mean; vs += dv * dv; }
    red[t] = vs; __syncthreads();
    for (int off = 128; off > 0; off >>= 1) {
        if (t < off) red[t] += red[t + off];
        __syncthreads();
    }
    const float rstd = rsqrtf(red[0] * (1.f / DD) + 1e-5f);
    #pragma unroll
    for (int i = 0; i < 3; i++) {
        int d = t + i * 256;
        g_h[(long)row * DD + d] = (vals[i] - mean) * rstd * w[d] + bvec[d];
    }
}

// ======================= host orchestration =======================
extern "C" void kernel_launch(void* const* d_in, const int* in_sizes, int n_in,
                              void* d_out, int out_size) {
    const int*   x    = (const int*)  d_in[0];
    const int*   ign  = (const int*)  d_in[1];
    const float* bpe  = (const float*)d_in[2];
    const float* pe   = (const float*)d_in[3];
    const float* Wq   = (const float*)d_in[4];
    const float* bq   = (const float*)d_in[5];
    const float* Wk   = (const float*)d_in[6];
    const float* bk   = (const float*)d_in[7];
    const float* Wv   = (const float*)d_in[8];
    const float* bv   = (const float*)d_in[9];
    const float* Wo   = (const float*)d_in[10];
    const float* bo   = (const float*)d_in[11];
    const float* W1   = (const float*)d_in[12];
    const float* b1   = (const float*)d_in[13];
    const float* W2   = (const float*)d_in[14];
    const float* b2   = (const float*)d_in[15];
    const float* ln1w = (const float*)d_in[16];
    const float* ln1b = (const float*)d_in[17];
    const float* ln2w = (const float*)d_in[18];
    const float* ln2b = (const float*)d_in[19];
    const float* Wout = (const float*)d_in[20];
    const float* bout = (const float*)d_in[21];
    float* out = (float*)d_out;

    float *gh, *gq, *gk, *gv, *gattn, *gproj, *gff1, *gff2;
    cudaGetSymbolAddress((void**)&gh,    g_h);
    cudaGetSymbolAddress((void**)&gq,    g_q);
    cudaGetSymbolAddress((void**)&gk,    g_k);
    cudaGetSymbolAddress((void**)&gv,    g_v);
    cudaGetSymbolAddress((void**)&gattn, g_attn);
    cudaGetSymbolAddress((void**)&gproj, g_proj);
    cudaGetSymbolAddress((void**)&gff1,  g_ff1);
    cudaGetSymbolAddress((void**)&gff2,  g_ff2);

    bf16 *wq_h, *wk_h, *wv_h, *wo_h, *w1_h, *w2_h, *wout_h, *act_h;
    bf16 *wq_l, *wk_l, *wv_l, *wo_l, *w1_l, *w2_l, *wout_l, *act_l;
    void* p;
    cudaGetSymbolAddress(&p, s_wq);   wq_h = (bf16*)p;   wq_l   = wq_h   + (long)LL*DD*DD;
    cudaGetSymbolAddress(&p, s_wk);   wk_h = (bf16*)p;   wk_l   = wk_h   + (long)LL*DD*DD;
    cudaGetSymbolAddress(&p, s_wv);   wv_h = (bf16*)p;   wv_l   = wv_h   + (long)LL*DD*DD;
    cudaGetSymbolAddress(&p, s_wo);   wo_h = (bf16*)p;   wo_l   = wo_h   + (long)LL*DD*DD;
    cudaGetSymbolAddress(&p, s_w1);   w1_h = (bf16*)p;   w1_l   = w1_h   + (long)LL*DD*FF;
    cudaGetSymbolAddress(&p, s_w2);   w2_h = (bf16*)p;   w2_l   = w2_h   + (long)LL*FF*DD;
    cudaGetSymbolAddress(&p, s_wout); wout_h = (bf16*)p; wout_l = wout_h + (long)VV*DD;
    cudaGetSymbolAddress(&p, s_act);  act_h = (bf16*)p;  act_l  = act_h  + (long)BB*SS*FF;

    cudaFuncSetAttribute(gemm_hmma, cudaFuncAttributeMaxDynamicSharedMemorySize, GH_SMEM);

    const int M = BB * SS;  // 2048
    dim3 tb32(32, 8);

    // weight conversion (transpose + hi/lo split)
    conv_transpose<<<dim3(HD/32, DD/32, LL*HH), tb32>>>(Wq, wq_h, wq_l, DD, HD,
                                                        (long)DD*HD, (long)HD*DD);
    conv_transpose<<<dim3(HD/32, DD/32, LL*HH), tb32>>>(Wk, wk_h, wk_l, DD, HD,
                                                        (long)DD*HD, (long)HD*DD);
    conv_transpose<<<dim3(HD/32, DD/32, LL*HH), tb32>>>(Wv, wv_h, wv_l, DD, HD,
                                                        (long)DD*HD, (long)HD*DD);
    conv_transpose<<<dim3(DD/32, DD/32, LL), tb32>>>(Wo, wo_h, wo_l, DD, DD,
                                                     (long)DD*DD, (long)DD*DD);
    conv_transpose<<<dim3(FF/32, DD/32, LL), tb32>>>(W1, w1_h, w1_l, DD, FF,
                                                     (long)DD*FF, (long)DD*FF);
    conv_transpose<<<dim3(DD/32, FF/32, LL), tb32>>>(W2, w2_h, w2_l, FF, DD,
                                                     (long)FF*DD, (long)FF*DD);
    conv_transpose<<<dim3(VV/32, DD/32, 1), tb32>>>(Wout, wout_h, wout_l, DD, VV, 0, 0);

    embed_kernel<<<(BB*SS*DD + 255) / 256, 256>>>(x, bpe, pe);

    const int nD = M * DD, nF = M * FF;

    for (int l = 0; l < LL; l++) {
        conv_act<<<(nD + 255)/256, 256>>>(gh, act_h, act_l, nD);
        gemm_hmma<<<dim3(16, DD/128), 256, GH_SMEM>>>(act_h, act_l,
            wq_h + (long)l*DD*DD, wq_l + (long)l*DD*DD, bq + (long)l*DD, gq, DD, DD);
        gemm_hmma<<<dim3(16, DD/128), 256, GH_SMEM>>>(act_h, act_l,
            wk_h + (long)l*DD*DD, wk_l + (long)l*DD*DD, bk + (long)l*DD, gk, DD, DD);
        gemm_hmma<<<dim3(16, DD/128), 256, GH_SMEM>>>(act_h, act_l,
            wv_h + (long)l*DD*DD, wv_l + (long)l*DD*DD, bv + (long)l*DD, gv, DD, DD);

        attn_kernel<<<BB * HH * SS, 128>>>(ign);

        conv_act<<<(nD + 255)/256, 256>>>(gattn, act_h, act_l, nD);
        gemm_hmma<<<dim3(16, DD/128), 256, GH_SMEM>>>(act_h, act_l,
            wo_h + (long)l*DD*DD, wo_l + (long)l*DD*DD, bo + (long)l*DD, gproj, DD, DD);
        add_ln_kernel<<<M, 256>>>(gproj, ln1w + (long)l*DD, ln1b + (long)l*DD, 0);

        conv_act<<<(nD + 255)/256, 256>>>(gh, act_h, act_l, nD);
        gemm_hmma<<<dim3(16, FF/128), 256, GH_SMEM>>>(act_h, act_l,
            w1_h + (long)l*DD*FF, w1_l + (long)l*DD*FF, b1 + (long)l*FF, gff1, FF, DD);
        conv_act<<<(nF + 255)/256, 256>>>(gff1, act_h, act_l, nF);
        gemm_hmma<<<dim3(16, DD/128), 256, GH_SMEM>>>(act_h, act_l,
            w2_h + (long)l*FF*DD, w2_l + (long)l*FF*DD, b2 + (long)l*DD, gff2, DD, FF);
        add_ln_kernel<<<M, 256>>>(gff2, ln2w + (long)l*DD, ln2b + (long)l*DD, 1);
    }

    conv_act<<<(nD + 255)/256, 256>>>(gh, act_h, act_l, nD);
    gemm_hmma<<<dim3(16, (VV + 127)/128), 256, GH_SMEM>>>(act_h, act_l,
        wout_h, wout_l, bout, out, VV, DD);
}

// round 5
// speedup vs baseline: 2.0726x; 1.1620x over previous
#include <cuda_runtime.h>
#include <cuda_bf16.h>
#include <math.h>
#include <stdint.h>

#define BB 16
#define SS 128
#define VV 40000
#define DD 768
#define HH 12
#define HD 64
#define FF 3072
#define LL 12

typedef __nv_bfloat16 bf16;

// ---------------- fp32 scratch ----------------
__device__ float g_h   [BB*SS*DD];
__device__ float g_qkv [BB*SS*3*DD];
__device__ float g_proj[BB*SS*DD];
__device__ float g_ff2 [BB*SS*DD];
__device__ float g_bqkv[LL*3*DD];

// ---------------- bf16 split weights [N][K] ----------------
__device__ bf16 s_wqkv[2][LL*3*DD*DD];
__device__ bf16 s_wo  [2][LL*DD*DD];
__device__ bf16 s_w1  [2][LL*DD*FF];
__device__ bf16 s_w2  [2][LL*FF*DD];
__device__ bf16 s_wout[2][VV*DD];
__device__ bf16 s_actA[2][BB*SS*FF];   // h (residual stream) hi/lo
__device__ bf16 s_actB[2][BB*SS*FF];   // attn-out / ff1-out hi/lo

// ======================= helpers =======================
__device__ __forceinline__ uint32_t smem_u32(const void* p) {
    uint32_t a;
    asm("{ .reg .u64 t; cvta.to.shared.u64 t, %1; cvt.u32.u64 %0, t; }" : "=r"(a) : "l"(p));
    return a;
}
__device__ __forceinline__ void cp16(uint32_t dst, const void* src) {
    asm volatile("cp.async.cg.shared.global [%0], [%1], 16;" :: "r"(dst), "l"(src) : "memory");
}
__device__ __forceinline__ void zero16(uint32_t dst) {
    asm volatile("st.shared.v4.b32 [%0], {%1,%1,%1,%1};" :: "r"(dst), "r"(0u) : "memory");
}
__device__ __forceinline__ void cp_commit() {
    asm volatile("cp.async.commit_group;" ::: "memory");
}
__device__ __forceinline__ void ldm4(uint32_t addr, uint32_t* r) {
    asm volatile("ldmatrix.sync.aligned.m8n8.x4.shared.b16 {%0,%1,%2,%3}, [%4];"
                 : "=r"(r[0]), "=r"(r[1]), "=r"(r[2]), "=r"(r[3]) : "r"(addr));
}
__device__ __forceinline__ void mma16816(float* d, const uint32_t* a, uint32_t b0, uint32_t b1) {
    asm volatile(
        "mma.sync.aligned.m16n8k16.row.col.f32.bf16.bf16.f32 "
        "{%0,%1,%2,%3}, {%4,%5,%6,%7}, {%8,%9}, {%0,%1,%2,%3};"
        : "+f"(d[0]), "+f"(d[1]), "+f"(d[2]), "+f"(d[3])
        : "r"(a[0]), "r"(a[1]), "r"(a[2]), "r"(a[3]), "r"(b0), "r"(b1));
}
__device__ __forceinline__ void split_bf16(float v, bf16& h, bf16& l) {
    h = __float2bfloat16(v);
    l = __float2bfloat16(v - __bfloat162float(h));
}

// ======================= small kernels =======================
__global__ void embed_kernel(const int* __restrict__ x,
                             const float* __restrict__ bpe,
                             const float* __restrict__ pe,
                             bf16* __restrict__ ah, bf16* __restrict__ al) {
    int idx = blockIdx.x * blockDim.x + threadIdx.x;
    if (idx >= BB*SS*DD) return;
    int d  = idx % DD;
    int bs = idx / DD;
    int s  = bs % SS;
    int tok = x[bs];
    float v = bpe[(long)tok*DD + d] + pe[s*DD + d];
    g_h[idx] = v;
    bf16 h, l; split_bf16(v, h, l);
    ah[idx] = h; al[idx] = l;
}

__global__ void concat_bias(const float* __restrict__ bq, const float* __restrict__ bk,
                            const float* __restrict__ bv) {
    int idx = blockIdx.x * blockDim.x + threadIdx.x;
    if (idx >= LL*3*DD) return;
    int l = idx / (3*DD), n = idx % (3*DD);
    float v;
    if (n < DD)          v = bq[l*DD + n];
    else if (n < 2*DD)   v = bk[l*DD + n - DD];
    else                 v = bv[l*DD + n - 2*DD];
    g_bqkv[idx] = v;
}

// transpose + split: src fp32 [R][C] -> dst bf16 [C][R] hi/lo, packed stores
__global__ void conv_transpose(const float* __restrict__ src, bf16* __restrict__ dhi,
                               bf16* __restrict__ dlo, int R, int C,
                               long srcZ, int Z2, long dstZ1, long dstZ2) {
    __shared__ float t[32][33];
    int c0 = blockIdx.x * 32, r0 = blockIdx.y * 32;
    long zs = (long)blockIdx.z * srcZ;
    long zd = (long)(blockIdx.z / Z2) * dstZ1 + (long)(blockIdx.z % Z2) * dstZ2;
    int tx = threadIdx.x, ty = threadIdx.y;   // (16,16)
    #pragma unroll
    for (int i = 0; i < 2; i++) {
        int r = ty + i * 16;
        float2 v = *reinterpret_cast<const float2*>(&src[zs + (long)(r0 + r) * C + c0 + tx*2]);
        t[tx*2][r] = v.x;
        t[tx*2+1][r] = v.y;
    }
    __syncthreads();
    #pragma unroll
    for (int i = 0; i < 2; i++) {
        int cc = ty + i * 16;
        float a0 = t[cc][tx*2], a1 = t[cc][tx*2+1];
        bf16 h0, l0, h1, l1;
        split_bf16(a0, h0, l0);
        split_bf16(a1, h1, l1);
        long o = zd + (long)(c0 + cc) * R + r0 + tx*2;
        *reinterpret_cast<__nv_bfloat162*>(&dhi[o]) = __nv_bfloat162(h0, h1);
        *reinterpret_cast<__nv_bfloat162*>(&dlo[o]) = __nv_bfloat162(l0, l1);
    }
}

// ======================= HMMA split-bf16 GEMM =======================
// C[2048,N] = (Ah+Al)[2048,K] x (Bh+Bl)^T + bias ; B stored [N][K].
// MI: m-frags per warp (4 -> TM=128, 2 -> TM=64). OUT: 0=fp32 C, 1=bf16 hi/lo.
#define TROW 80

template<int TM>
__device__ __forceinline__ void load_chunk(
    uint32_t base, const bf16* __restrict__ Ah, const bf16* __restrict__ Al,
    const bf16* __restrict__ Bh, const bf16* __restrict__ Bl,
    int m0, int n0, int N, int K, int c, int tid)
{
    const uint32_t A_BYTES = TM * TROW;
    const uint32_t BUF = (2 * TM + 256) * TROW;
    uint32_t bb = base + (uint32_t)(c & 1) * BUF;
    int k0 = c << 5;
    #pragma unroll
    for (int i = 0; i < TM/64; i++) {
        int ci  = tid + i * 256;
        int row = ci >> 2, kq = ci & 3;
        uint32_t doff = (uint32_t)(row * TROW + kq * 16);
        long aoff = (long)(m0 + row) * K + k0 + kq * 8;
        cp16(bb + doff, Ah + aoff);
        cp16(bb + A_BYTES + doff, Al + aoff);
    }
    #pragma unroll
    for (int i = 0; i < 2; i++) {
        int ci  = tid + i * 256;
        int row = ci >> 2, kq = ci & 3;
        uint32_t doff = (uint32_t)(row * TROW + kq * 16);
        int nr = n0 + row;
        if (nr < N) {
            long boff = (long)nr * K + k0 + kq * 8;
            cp16(bb + 2*A_BYTES + doff, Bh + boff);
            cp16(bb + 2*A_BYTES + 128*TROW + doff, Bl + boff);
        } else {
            zero16(bb + 2*A_BYTES + doff);
            zero16(bb + 2*A_BYTES + 128*TROW + doff);
        }
    }
}

template<int MI, int OUT>
__global__ __launch_bounds__(256, 2) void gemm_hmma(
    const bf16* __restrict__ Ah, const bf16* __restrict__ Al,
    const bf16* __restrict__ Bh, const bf16* __restrict__ Bl,
    const float* __restrict__ bias, float* __restrict__ C,
    bf16* __restrict__ Oh, bf16* __restrict__ Ol,
    int N, int K)
{
    constexpr int TM = MI * 32;
    const uint32_t A_BYTES = TM * TROW;
    const uint32_t BUF = (2 * TM + 256) * TROW;
    extern __shared__ char smem[];
    const uint32_t base = smem_u32(smem);
    const int tid  = threadIdx.x;
    const int lane = tid & 31;
    const int w    = tid >> 5;
    const int wm   = w & 1;
    const int wn   = w >> 1;
    const int m0 = blockIdx.x * TM, n0 = blockIdx.y * 128;
    const int nCh = K >> 5;

    float acc[MI][4][4];
    #pragma unroll
    for (int i = 0; i < MI; i++)
        #pragma unroll
        for (int j = 0; j < 4; j++)
            #pragma unroll
            for (int q = 0; q < 4; q++) acc[i][j][q] = 0.f;

    const uint32_t a_loff = (uint32_t)((lane & 15) * TROW + ((lane >> 4) << 3) * 2);
    const uint32_t b_loff = (uint32_t)((((lane & 7) + ((lane & 16) ? 8 : 0)) * TROW) +
                                       ((lane & 8) ? 16 : 0));

    load_chunk<TM>(base, Ah, Al, Bh, Bl, m0, n0, N, K, 0, tid);
    cp_commit();

    for (int c = 0; c < nCh; c++) {
        if (c + 1 < nCh) {
            load_chunk<TM>(base, Ah, Al, Bh, Bl, m0, n0, N, K, c + 1, tid);
            cp_commit();
            asm volatile("cp.async.wait_group 1;" ::: "memory");
        } else {
            asm volatile("cp.async.wait_group 0;" ::: "memory");
        }
        __syncthreads();

        uint32_t bb = base + (uint32_t)(c & 1) * BUF;
        uint32_t aH = bb + (uint32_t)(wm * (MI * 16)) * TROW;
        uint32_t aL = aH + A_BYTES;
        uint32_t bH = bb + 2 * A_BYTES + (uint32_t)(wn * 32) * TROW;
        uint32_t bL = bH + 128 * TROW;

        #pragma unroll
        for (int ks = 0; ks < 2; ks++) {
            const uint32_t koff = (uint32_t)(ks * 32);
            uint32_t bh[2][4], bl[2][4];
            #pragma unroll
            for (int g = 0; g < 2; g++) {
                ldm4(bH + (uint32_t)(g * 16) * TROW + b_loff + koff, bh[g]);
                ldm4(bL + (uint32_t)(g * 16) * TROW + b_loff + koff, bl[g]);
            }
            #pragma unroll
            for (int mi = 0; mi < MI; mi++) {
                uint32_t ah[4], al[4];
                ldm4(aH + (uint32_t)(mi * 16) * TROW + a_loff + koff, ah);
                ldm4(aL + (uint32_t)(mi * 16) * TROW + a_loff + koff, al);
                #pragma unroll
                for (int ni = 0; ni < 4; ni++) {
                    const int g = ni >> 1, o = (ni & 1) * 2;
                    mma16816(acc[mi][ni], ah, bh[g][o], bh[g][o + 1]);
                    mma16816(acc[mi][ni], ah, bl[g][o], bl[g][o + 1]);
                    mma16816(acc[mi][ni], al, bh[g][o], bh[g][o + 1]);
                }
            }
        }
        __syncthreads();
    }

    // epilogue
    #pragma unroll
    for (int mi = 0; mi < MI; mi++) {
        int row = m0 + wm * (MI * 16) + mi * 16 + (lane >> 2);
        #pragma unroll
        for (int ni = 0; ni < 4; ni++) {
            int col = n0 + wn * 32 + ni * 8 + ((lane & 3) << 1);
            if (col < N) {
                float bx = bias[col], by = bias[col + 1];
                float v00 = acc[mi][ni][0] + bx, v01 = acc[mi][ni][1] + by;
                float v10 = acc[mi][ni][2] + bx, v11 = acc[mi][ni][3] + by;
                if (OUT == 0) {
                    *reinterpret_cast<float2*>(C + (long)row * N + col)       = make_float2(v00, v01);
                    *reinterpret_cast<float2*>(C + (long)(row + 8) * N + col) = make_float2(v10, v11);
                } else {
                    bf16 h0,l0,h1,l1,h2,l2,h3,l3;
                    split_bf16(v00, h0, l0); split_bf16(v01, h1, l1);
                    split_bf16(v10, h2, l2); split_bf16(v11, h3, l3);
                    *reinterpret_cast<__nv_bfloat162*>(Oh + (long)row * N + col)       = __nv_bfloat162(h0, h1);
                    *reinterpret_cast<__nv_bfloat162*>(Ol + (long)row * N + col)       = __nv_bfloat162(l0, l1);
                    *reinterpret_cast<__nv_bfloat162*>(Oh + (long)(row + 8) * N + col) = __nv_bfloat162(h2, h3);
                    *reinterpret_cast<__nv_bfloat162*>(Ol + (long)(row + 8) * N + col) = __nv_bfloat162(l2, l3);
                }
            }
        }
    }
}

// ======================= attention (strided qkv, bf16 hi/lo out) =======================
__global__ __launch_bounds__(128) void attn_kernel(const int* __restrict__ ignore,
                                                   bf16* __restrict__ oh,
                                                   bf16* __restrict__ ol) {
    const int qi = blockIdx.x & (SS - 1);
    const int h  = (blockIdx.x >> 7) % HH;
    const int b  = blockIdx.x / (SS * HH);
    const int t  = threadIdx.x;
    const int QW = 3 * DD;   // qkv row width

    __shared__ float qrow[HD];
    __shared__ float p[SS];
    __shared__ float red[SS];

    const float* qptr = g_qkv + ((long)(b * SS + qi) * QW + h * HD);
    if (t < HD) qrow[t] = qptr[t];
    __syncthreads();

    const bool allowed = (t <= qi) && (ignore[b * SS + t] == 0 || t == qi);
    float score = -INFINITY;
    if (allowed) {
        const float* kptr = g_qkv + ((long)(b * SS + t) * QW + DD + h * HD);
        float s = 0.f;
        #pragma unroll
        for (int e = 0; e < HD; e++) s += qrow[e] * kptr[e];
        score = s * 0.125f;
    }
    red[t] = score; __syncthreads();
    for (int off = 64; off > 0; off >>= 1) {
        if (t < off) red[t] = fmaxf(red[t], red[t + off]);
        __syncthreads();
    }
    const float mx = red[0];
    __syncthreads();
    const float e = allowed ? expf(score - mx) : 0.f;
    p[t] = e; red[t] = e; __syncthreads();
    for (int off = 64; off > 0; off >>= 1) {
        if (t < off) red[t] += red[t + off];
        __syncthreads();
    }
    const float inv = 1.f / red[0];
    if (t < HD) {
        const float* vbase = g_qkv + ((long)b * SS * QW + 2 * DD + h * HD + t);
        float o = 0.f;
        #pragma unroll 4
        for (int k = 0; k < SS; k++) o += p[k] * vbase[(long)k * QW];
        o *= inv;
        long oidx = (long)(b * SS + qi) * DD + h * HD + t;
        bf16 hh, ll; split_bf16(o, hh, ll);
        oh[oidx] = hh; ol[oidx] = ll;
    }
}

// ======================= residual (+GELU) + LayerNorm + split =======================
__global__ __launch_bounds__(256) void add_ln_kernel(
    const float* __restrict__ res_in,
    const float* __restrict__ w, const float* __restrict__ bvec,
    bf16* __restrict__ ah, bf16* __restrict__ al,
    int dogelu) {
    const int row = blockIdx.x;
    const int t = threadIdx.x;
    __shared__ float red[256];

    float vals[3];
    float sum = 0.f;
    #pragma unroll
    for (int i = 0; i < 3; i++) {
        int d = t + i * 256;
        float r = res_in[(long)row * DD + d];
        if (dogelu) r = 0.5f * r * (1.f + erff(r * 0.70710678118f));
        float v = g_h[(long)row * DD + d] + r;
        vals[i] = v;
        sum += v;
    }
    red[t] = sum; __syncthreads();
    for (int off = 128; off > 0; off >>= 1) {
        if (t < off) red[t] += red[t + off];
        __syncthreads();
    }
    const float mean = red[0] * (1.f / DD);
    __syncthreads();
    float vs = 0.f;
    #pragma unroll
    for (int i = 0; i < 3; i++) { float dv = vals[i] - mean; vs += dv * dv; }
    red[t] = vs; __syncthreads();
    for (int off = 128; off > 0; off >>= 1) {
        if (t < off) red[t] += red[t + off];
        __syncthreads();
    }
    const float rstd = rsqrtf(red[0] * (1.f / DD) + 1e-5f);
    #pragma unroll
    for (int i = 0; i < 3; i++) {
        int d = t + i * 256;
        float v = (vals[i] - mean) * rstd * w[d] + bvec[d];
        g_h[(long)row * DD + d] = v;
        bf16 hh, ll; split_bf16(v, hh, ll);
        ah[(long)row * DD + d] = hh;
        al[(long)row * DD + d] = ll;
    }
}

// ======================= host orchestration =======================
extern "C" void kernel_launch(void* const* d_in, const int* in_sizes, int n_in,
                              void* d_out, int out_size) {
    const int*   x    = (const int*)  d_in[0];
    const int*   ign  = (const int*)  d_in[1];
    const float* bpe  = (const float*)d_in[2];
    const float* pe   = (const float*)d_in[3];
    const float* Wq   = (const float*)d_in[4];
    const float* bq   = (const float*)d_in[5];
    const float* Wk   = (const float*)d_in[6];
    const float* bk   = (const float*)d_in[7];
    const float* Wv   = (const float*)d_in[8];
    const float* bv   = (const float*)d_in[9];
    const float* Wo   = (const float*)d_in[10];
    const float* bo   = (const float*)d_in[11];
    const float* W1   = (const float*)d_in[12];
    const float* b1   = (const float*)d_in[13];
    const float* W2   = (const float*)d_in[14];
    const float* b2   = (const float*)d_in[15];
    const float* ln1w = (const float*)d_in[16];
    const float* ln1b = (const float*)d_in[17];
    const float* ln2w = (const float*)d_in[18];
    const float* ln2b = (const float*)d_in[19];
    const float* Wout = (const float*)d_in[20];
    const float* bout = (const float*)d_in[21];
    float* out = (float*)d_out;

    float *gh, *gqkv, *gproj, *gff2, *gbqkv;
    cudaGetSymbolAddress((void**)&gh,    g_h);
    cudaGetSymbolAddress((void**)&gqkv,  g_qkv);
    cudaGetSymbolAddress((void**)&gproj, g_proj);
    cudaGetSymbolAddress((void**)&gff2,  g_ff2);
    cudaGetSymbolAddress((void**)&gbqkv, g_bqkv);

    bf16 *wqkv_h, *wo_h, *w1_h, *w2_h, *wout_h, *actA_h, *actB_h;
    bf16 *wqkv_l, *wo_l, *w1_l, *w2_l, *wout_l, *actA_l, *actB_l;
    void* p;
    cudaGetSymbolAddress(&p, s_wqkv); wqkv_h = (bf16*)p; wqkv_l = wqkv_h + (long)LL*3*DD*DD;
    cudaGetSymbolAddress(&p, s_wo);   wo_h = (bf16*)p;   wo_l   = wo_h   + (long)LL*DD*DD;
    cudaGetSymbolAddress(&p, s_w1);   w1_h = (bf16*)p;   w1_l   = w1_h   + (long)LL*DD*FF;
    cudaGetSymbolAddress(&p, s_w2);   w2_h = (bf16*)p;   w2_l   = w2_h   + (long)LL*FF*DD;
    cudaGetSymbolAddress(&p, s_wout); wout_h = (bf16*)p; wout_l = wout_h + (long)VV*DD;
    cudaGetSymbolAddress(&p, s_actA); actA_h = (bf16*)p; actA_l = actA_h + (long)BB*SS*FF;
    cudaGetSymbolAddress(&p, s_actB); actB_h = (bf16*)p; actB_l = actB_h + (long)BB*SS*FF;

    const int SM128 = (2*128 + 256) * TROW * 2;   // 81920
    const int SM64  = (2*64  + 256) * TROW * 2;   // 61440
    cudaFuncSetAttribute(gemm_hmma<4,0>, cudaFuncAttributeMaxDynamicSharedMemorySize, SM128);
    cudaFuncSetAttribute(gemm_hmma<4,1>, cudaFuncAttributeMaxDynamicSharedMemorySize, SM128);
    cudaFuncSetAttribute(gemm_hmma<2,0>, cudaFuncAttributeMaxDynamicSharedMemorySize, SM64);

    const int M = BB * SS;  // 2048
    dim3 tb16(16, 16);

    // ---- weight conversion ----
    // QKV concat: dst [l][which*768 + h*64][768]
    conv_transpose<<<dim3(HD/32, DD/32, LL*HH), tb16>>>(Wq, wqkv_h + 0L*DD*DD, wqkv_l + 0L*DD*DD,
        DD, HD, (long)DD*HD, HH, (long)3*DD*DD, (long)HD*DD);
    conv_transpose<<<dim3(HD/32, DD/32, LL*HH), tb16>>>(Wk, wqkv_h + 1L*DD*DD, wqkv_l + 1L*DD*DD,
        DD, HD, (long)DD*HD, HH, (long)3*DD*DD, (long)HD*DD);
    conv_transpose<<<dim3(HD/32, DD/32, LL*HH), tb16>>>(Wv, wqkv_h + 2L*DD*DD, wqkv_l + 2L*DD*DD,
        DD, HD, (long)DD*HD, HH, (long)3*DD*DD, (long)HD*DD);
    conv_transpose<<<dim3(DD/32, DD/32, LL), tb16>>>(Wo, wo_h, wo_l,
        DD, DD, (long)DD*DD, 1, (long)DD*DD, 0);
    conv_transpose<<<dim3(FF/32, DD/32, LL), tb16>>>(W1, w1_h, w1_l,
        DD, FF, (long)DD*FF, 1, (long)DD*FF, 0);
    conv_transpose<<<dim3(DD/32, FF/32, LL), tb16>>>(W2, w2_h, w2_l,
        FF, DD, (long)FF*DD, 1, (long)FF*DD, 0);
    conv_transpose<<<dim3(VV/32, DD/32, 1), tb16>>>(Wout, wout_h, wout_l,
        DD, VV, 0, 1, 0, 0);
    concat_bias<<<(LL*3*DD + 255)/256, 256>>>(bq, bk, bv);

    embed_kernel<<<(BB*SS*DD + 255)/256, 256>>>(x, bpe, pe, actA_h, actA_l);

    for (int l = 0; l < LL; l++) {
        // fused QKV: [2048,768] x [2304,768]^T -> g_qkv
        gemm_hmma<4,0><<<dim3(M/128, (3*DD)/128), 256, SM128>>>(actA_h, actA_l,
            wqkv_h + (long)l*3*DD*DD, wqkv_l + (long)l*3*DD*DD,
            gbqkv + (long)l*3*DD, gqkv, nullptr, nullptr, 3*DD, DD);

        attn_kernel<<<BB*HH*SS, 128>>>(ign, actB_h, actB_l);

        gemm_hmma<2,0><<<dim3(M/64, DD/128), 256, SM64>>>(actB_h, actB_l,
            wo_h + (long)l*DD*DD, wo_l + (long)l*DD*DD,
            bo + (long)l*DD, gproj, nullptr, nullptr, DD, DD);
        add_ln_kernel<<<M, 256>>>(gproj, ln1w + (long)l*DD, ln1b + (long)l*DD,
                                  actA_h, actA_l, 0);

        gemm_hmma<4,1><<<dim3(M/128, FF/128), 256, SM128>>>(actA_h, actA_l,
            w1_h + (long)l*DD*FF, w1_l + (long)l*DD*FF,
            b1 + (long)l*FF, nullptr, actB_h, actB_l, FF, DD);
        gemm_hmma<2,0><<<dim3(M/64, DD/128), 256, SM64>>>(actB_h, actB_l,
            w2_h + (long)l*FF*DD, w2_l + (long)l*FF*DD,
            b2 + (long)l*DD, gff2, nullptr, nullptr, DD, FF);
        add_ln_kernel<<<M, 256>>>(gff2, ln2w + (long)l*DD, ln2b + (long)l*DD,
                                  actA_h, actA_l, 1);
    }

    gemm_hmma<4,0><<<dim3(M/128, (VV + 127)/128), 256, SM128>>>(actA_h, actA_l,
        wout_h, wout_l, bout, out, nullptr, nullptr, VV, DD);
}